// round 1
// baseline (speedup 1.0000x reference)
#include <cuda_runtime.h>
#include <math.h>

#define NB 64
#define NL 1024
#define ND 1024
#define EPSF 1e-15f
#define PROJ_EPS 4e-3f

// ---------------- scratch (device globals: no allocation allowed) ----------------
__device__ float g_combined[NB * 2 * ND];   // [b, 0:D)=mixl (logmap), [b, D:2D)=q
__device__ float g_scores[NB * NL];
__device__ float g_aw[NB * NL];             // hyperbolic attention weights (also output #2)
__device__ float g_bt[NB * NL];             // projected expmap0(exp(-ab*dt))
__device__ float g_btn[NB];                 // per-b norm of projected bt
__device__ float g_u[NB * ND];
__device__ float g_v[NB * ND];
__device__ float g_dl[NB * ND];             // delta (sign carrier for relu indicator)
__device__ float g_lam[NB * NL];
__device__ float g_nom[NB * ND];

__device__ __forceinline__ float artanh_c(float x) {
    x = fminf(fmaxf(x, -1.0f + 1e-7f), 1.0f - 1e-7f);
    return atanhf(x);
}

template <int NT>
__device__ __forceinline__ float blk_sum(float v, float* sb) {
    int t = threadIdx.x;
    sb[t] = v; __syncthreads();
#pragma unroll
    for (int s = NT / 2; s > 0; s >>= 1) {
        if (t < s) sb[t] += sb[t + s];
        __syncthreads();
    }
    float r = sb[0]; __syncthreads();
    return r;
}

template <int NT>
__device__ __forceinline__ float blk_max(float v, float* sb) {
    int t = threadIdx.x;
    sb[t] = v; __syncthreads();
#pragma unroll
    for (int s = NT / 2; s > 0; s >>= 1) {
        if (t < s) sb[t] = fmaxf(sb[t], sb[t + s]);
        __syncthreads();
    }
    float r = sb[0]; __syncthreads();
    return r;
}

// ---------------- A: q = query @ W_in^T  -> g_combined[b, D:2D) ----------------
// block (64,4): x = batch b, y = one of 4 output features. grid = D/4.
__global__ void kA(const float* __restrict__ query, const float* __restrict__ W_in) {
    int b = threadIdx.x;
    int e = blockIdx.x * 4 + threadIdx.y;
    const float4* q4 = (const float4*)(query + (size_t)b * ND);
    const float4* w4 = (const float4*)(W_in + (size_t)e * ND);
    float acc = 0.f;
#pragma unroll 4
    for (int k = 0; k < ND / 4; k++) {
        float4 a = q4[k], w = w4[k];
        acc += a.x * w.x + a.y * w.y + a.z * w.z + a.w * w.w;
    }
    g_combined[(size_t)b * 2 * ND + ND + e] = acc;
}

// ---------------- B: scores[b,l] = dot(q[b], ctx[b,l,:]) ----------------
// grid (L/8, B), 256 thr = 8 warps, warp per l.
__global__ void kB(const float* __restrict__ ctx) {
    __shared__ float sq[ND];
    int b = blockIdx.y;
    int warp = threadIdx.x >> 5, lane = threadIdx.x & 31;
    ((float4*)sq)[threadIdx.x] = ((const float4*)(g_combined + (size_t)b * 2 * ND + ND))[threadIdx.x];
    __syncthreads();
    int l = blockIdx.x * 8 + warp;
    const float4* c4 = (const float4*)(ctx + ((size_t)(b * NL + l)) * ND);
    const float4* s4 = (const float4*)sq;
    float acc = 0.f;
#pragma unroll
    for (int k = 0; k < 8; k++) {
        int i = k * 32 + lane;
        float4 cv = c4[i], qv = s4[i];
        acc += cv.x * qv.x + cv.y * qv.y + cv.z * qv.z + cv.w * qv.w;
    }
#pragma unroll
    for (int o = 16; o > 0; o >>= 1) acc += __shfl_down_sync(0xffffffffu, acc, o);
    if (lane == 0) g_scores[b * NL + l] = acc;
}

// ---------------- C: softmax + expmap0/project (aw), bt pipeline ----------------
// one block per b, 1024 threads (one per l).
__global__ void kC(const float* __restrict__ dt, const float* __restrict__ cp,
                   const float* __restrict__ ab, float* __restrict__ out_aw) {
    __shared__ float sb[1024];
    int b = blockIdx.x, t = threadIdx.x;
    float c = cp[0], sc = sqrtf(c);
    float maxn = (1.0f - PROJ_EPS) / sc;

    float s = g_scores[b * NL + t];
    float mx = blk_max<1024>(s, sb);
    float e = expf(s - mx);
    float sum = blk_sum<1024>(e, sb);
    float aw = e / sum;

    float n = fmaxf(sqrtf(blk_sum<1024>(aw * aw, sb)), EPSF);
    float awh = tanhf(sc * n) / (sc * n) * aw;
    float nh = fmaxf(sqrtf(blk_sum<1024>(awh * awh, sb)), EPSF);
    if (nh > maxn) awh *= maxn / nh;
    g_aw[b * NL + t] = awh;
    out_aw[b * NL + t] = awh;

    float braw = expf(-ab[b] * dt[b * NL + t]);
    float bn = fmaxf(sqrtf(blk_sum<1024>(braw * braw, sb)), EPSF);
    float bth = tanhf(sc * bn) / (sc * bn) * braw;
    float bh = fmaxf(sqrtf(blk_sum<1024>(bth * bth, sb)), EPSF);
    if (bh > maxn) bth *= maxn / bh;
    g_bt[b * NL + t] = bth;
    if (t == 0) g_btn[b] = fminf(bh, maxn);   // norm of projected bt (>= EPS already)
}

// ---------------- D: per-(b,d) column stats -> scalars u, v, delta ----------------
// grid (D/256, B), 256 threads; thread owns one d, loops l (coalesced over d).
__global__ void kD(const float* __restrict__ ctx, const float* __restrict__ cp,
                   const float* __restrict__ ae) {
    __shared__ float saw[NL], sbt[NL];
    int b = blockIdx.y, t = threadIdx.x;
    for (int i = t; i < NL; i += 256) { saw[i] = g_aw[b * NL + i]; sbt[i] = g_bt[b * NL + i]; }
    __syncthreads();
    int d = blockIdx.x * 256 + t;
    const float* cb = ctx + (size_t)b * NL * ND + d;

    float sx2 = 0.f, swx2 = 0.f, s2p = 0.f, s2n = 0.f, sxp = 0.f, sxn = 0.f;
#pragma unroll 4
    for (int l = 0; l < NL; l++) {
        float x = cb[(size_t)l * ND];
        float a = saw[l];
        float ax = a * x;
        float g = sbt[l] * ax;
        sx2 += x * x;
        swx2 += ax * ax;
        if (g > 0.f)      { s2p += g * g; sxp += ax * g; }
        else if (g < 0.f) { s2n += g * g; sxn += ax * g; }
    }

    float c = cp[0], sc = sqrtf(c);
    float maxn = (1.0f - PROJ_EPS) / sc;

    // step 5: mix = project(mobius_pointwise_mul(aw, ctx_t))  -> mix = alpha*aw*ctx
    float xn  = fmaxf(sqrtf(sx2), EPSF);
    float wxnr = sqrtf(swx2);
    float wxn = fmaxf(wxnr, EPSF);
    float s1 = tanhf(wxn / xn * artanh_c(sc * xn)) / (wxn * sc);
    float n1 = fmaxf(fabsf(s1) * wxnr, EPSF);
    float alpha = s1 * (n1 > maxn ? maxn / n1 : 1.0f);
    float nmixr = fabsf(alpha) * wxnr;

    // step 7: tmp = project(mobius_pointwise_mul(ae, mix)) -> tmp = T*aw*ctx
    float aeb = ae[b];
    float xn7 = fmaxf(nmixr, EPSF);
    float wxn7 = fmaxf(fabsf(aeb) * nmixr, EPSF);
    float t7 = tanhf(wxn7 / xn7 * artanh_c(sc * xn7)) / (wxn7 * sc);
    float n7 = fmaxf(fabsf(t7 * aeb) * nmixr, EPSF);
    float T = t7 * aeb * alpha * (n7 > maxn ? maxn / n7 : 1.0f);

    // step 8: tmp = project(mobius_pointwise_mul(tmp, bt)) -> delta*aw*bt*ctx
    float m8r = sqrtf(s2p + s2n);
    float xn8 = g_btn[b];
    float wxn8 = fmaxf(fabsf(T) * m8r, EPSF);
    float t8 = tanhf(wxn8 / xn8 * artanh_c(sc * xn8)) / (wxn8 * sc);
    float dpre = t8 * T;
    float n8 = fmaxf(fabsf(dpre) * m8r, EPSF);
    float dl = dpre * (n8 > maxn ? maxn / n8 : 1.0f);

    // step 10: mix = project(mobius_add(mix, relu(tmp)))
    float x2 = alpha * alpha * swx2;
    bool pos = (dl > 0.f);
    float S2 = pos ? s2p : s2n;
    float SX = pos ? sxp : sxn;
    float y2 = dl * dl * S2;
    float xy = alpha * dl * SX;
    float A  = 1.0f + 2.0f * c * xy + c * y2;
    float Bc = 1.0f - c * x2;
    float den = fmaxf(1.0f + 2.0f * c * xy + c * c * x2 * y2, EPSF);
    float nn2 = (A * A * x2 + 2.0f * A * Bc * xy + Bc * Bc * y2) / (den * den);
    float n10 = fmaxf(sqrtf(fmaxf(nn2, 0.f)), EPSF);
    float p10 = (n10 > maxn) ? maxn / n10 : 1.0f;

    g_u[b * ND + d]  = p10 * A * alpha / den;
    g_v[b * ND + d]  = p10 * Bc * dl / den;
    g_dl[b * ND + d] = dl;
}

// ---------------- E1: lambda[b,l] = 2 / max(1 - c * sum_d mix^2, EPS) ----------------
// grid (L, B), 256 threads; one float4 of ctx row per thread.
__global__ void kE1(const float* __restrict__ ctx, const float* __restrict__ cp) {
    __shared__ float sb[256];
    int b = blockIdx.y, l = blockIdx.x, t = threadIdx.x;
    float c = cp[0];
    float awl = g_aw[b * NL + l], btl = g_bt[b * NL + l];
    const float4* x4 = (const float4*)(ctx + ((size_t)(b * NL + l)) * ND);
    const float4* u4 = (const float4*)(g_u + (size_t)b * ND);
    const float4* v4 = (const float4*)(g_v + (size_t)b * ND);
    const float4* d4 = (const float4*)(g_dl + (size_t)b * ND);
    float4 x = x4[t], u = u4[t], v = v4[t], dl = d4[t];
    float s = 0.f;
    {
        float g, m;
        g = awl * btl * x.x; m = u.x * awl * x.x + ((dl.x * g) > 0.f ? v.x * g : 0.f); s += m * m;
        g = awl * btl * x.y; m = u.y * awl * x.y + ((dl.y * g) > 0.f ? v.y * g : 0.f); s += m * m;
        g = awl * btl * x.z; m = u.z * awl * x.z + ((dl.z * g) > 0.f ? v.z * g : 0.f); s += m * m;
        g = awl * btl * x.w; m = u.w * awl * x.w + ((dl.w * g) > 0.f ? v.w * g : 0.f); s += m * m;
    }
    s = blk_sum<256>(s, sb);
    if (t == 0) g_lam[b * NL + l] = 2.0f / fmaxf(1.0f - c * s, EPSF);
}

// ---------------- E2: nom[b,d] = sum_l lam[l] * mix[b,d,l] ----------------
__global__ void kE2(const float* __restrict__ ctx) {
    __shared__ float saw[NL], sbt[NL], slam[NL];
    int b = blockIdx.y, t = threadIdx.x;
    for (int i = t; i < NL; i += 256) {
        saw[i] = g_aw[b * NL + i];
        sbt[i] = g_bt[b * NL + i];
        slam[i] = g_lam[b * NL + i];
    }
    __syncthreads();
    int d = blockIdx.x * 256 + t;
    float u = g_u[b * ND + d], v = g_v[b * ND + d], dl = g_dl[b * ND + d];
    const float* cb = ctx + (size_t)b * NL * ND + d;
    float nom = 0.f;
#pragma unroll 4
    for (int l = 0; l < NL; l++) {
        float x = cb[(size_t)l * ND];
        float a = saw[l];
        float g = sbt[l] * a * x;
        float m = u * a * x + ((dl * g) > 0.f ? v * g : 0.f);
        nom += slam[l] * m;
    }
    g_nom[b * ND + d] = nom;
}

// ---------------- F: midpoint epilogue -> mixl = logmap0(mobius_scalar_mul(0.5, tm)) ----------------
__global__ void kF(const float* __restrict__ cp) {
    __shared__ float sb[1024];
    int b = blockIdx.x, t = threadIdx.x;
    float c = cp[0], sc = sqrtf(c);
    float lam = g_lam[b * NL + t];
    float den = blk_sum<1024>(lam - 1.0f, sb);
    den = (den >= 0.f) ? fmaxf(den, 1e-10f) : fminf(den, -1e-10f);
    float tm = g_nom[b * ND + t] / den;
    float nr = sqrtf(blk_sum<1024>(tm * tm, sb));
    float n = fmaxf(nr, EPSF);
    float cf = tanhf(0.5f * artanh_c(sc * n)) / (sc * n);
    float nf = fmaxf(fabsf(cf) * nr, EPSF);
    float lc = artanh_c(sc * nf) / (sc * nf);
    g_combined[(size_t)b * 2 * ND + t] = lc * cf * tm;
}

// ---------------- G: out = tanh(combined @ W_out^T) ----------------
__global__ void kG(const float* __restrict__ W_out, float* __restrict__ out) {
    int b = threadIdx.x;
    int d = blockIdx.x * 4 + threadIdx.y;
    const float4* cb4 = (const float4*)(g_combined + (size_t)b * 2 * ND);
    const float4* w4  = (const float4*)(W_out + (size_t)d * 2 * ND);
    float acc = 0.f;
#pragma unroll 4
    for (int k = 0; k < 2 * ND / 4; k++) {
        float4 a = cb4[k], w = w4[k];
        acc += a.x * w.x + a.y * w.y + a.z * w.z + a.w * w.w;
    }
    out[b * ND + d] = tanhf(acc);
}

// ---------------- launch ----------------
extern "C" void kernel_launch(void* const* d_in, const int* in_sizes, int n_in,
                              void* d_out, int out_size) {
    const float* query = (const float*)d_in[0];
    const float* ctx   = (const float*)d_in[1];
    const float* dt    = (const float*)d_in[2];
    const float* cp    = (const float*)d_in[3];
    const float* W_in  = (const float*)d_in[4];
    const float* W_out = (const float*)d_in[5];
    const float* ae    = (const float*)d_in[6];
    const float* ab    = (const float*)d_in[7];
    float* out = (float*)d_out;

    kA<<<ND / 4, dim3(64, 4)>>>(query, W_in);
    kB<<<dim3(NL / 8, NB), 256>>>(ctx);
    kC<<<NB, 1024>>>(dt, cp, ab, out + NB * ND);   // aw written to second output region
    kD<<<dim3(ND / 256, NB), 256>>>(ctx, cp, ae);
    kE1<<<dim3(NL, NB), 256>>>(ctx, cp);
    kE2<<<dim3(ND / 256, NB), 256>>>(ctx);
    kF<<<NB, 1024>>>(cp);
    kG<<<ND / 4, dim3(64, 4)>>>(W_out, out);
}

// round 2
// speedup vs baseline: 1.4336x; 1.4336x over previous
#include <cuda_runtime.h>
#include <math.h>

#define NB 64
#define NL 1024
#define ND 1024
#define SPLIT 16
#define CH (NL / SPLIT)       // 64 l per chunk
#define EPSF 1e-15f
#define PROJ_EPS 4e-3f

// ---------------- scratch (device globals) ----------------
__device__ float g_combined[NB * 2 * ND];   // [b,0:D)=mixl, [b,D:2D)=q
__device__ float g_scores[NB * NL];
__device__ float g_aw[NB * NL];
__device__ float g_bt[NB * NL];
__device__ float g_btn[NB];
__device__ float g_u[NB * ND];
__device__ float g_v[NB * ND];
__device__ float g_dl[NB * ND];
__device__ float g_lam[NB * NL];
__device__ float g_part[6 * NB * SPLIT * ND];   // kD partials: [k][b][s][d]
__device__ float g_nomp[NB * SPLIT * ND];       // kE2 partials

__device__ __forceinline__ float artanh_c(float x) {
    x = fminf(fmaxf(x, -1.0f + 1e-7f), 1.0f - 1e-7f);
    return atanhf(x);
}

template <int NT>
__device__ __forceinline__ float blk_sum(float v, float* sb) {
    int t = threadIdx.x;
    sb[t] = v; __syncthreads();
#pragma unroll
    for (int s = NT / 2; s > 0; s >>= 1) {
        if (t < s) sb[t] += sb[t + s];
        __syncthreads();
    }
    float r = sb[0]; __syncthreads();
    return r;
}

template <int NT>
__device__ __forceinline__ float blk_max(float v, float* sb) {
    int t = threadIdx.x;
    sb[t] = v; __syncthreads();
#pragma unroll
    for (int s = NT / 2; s > 0; s >>= 1) {
        if (t < s) sb[t] = fmaxf(sb[t], sb[t + s]);
        __syncthreads();
    }
    float r = sb[0]; __syncthreads();
    return r;
}

// ---------------- A: q = query @ W_in^T ----------------
__global__ void kA(const float* __restrict__ query, const float* __restrict__ W_in) {
    int b = threadIdx.x;
    int e = blockIdx.x * 4 + threadIdx.y;
    const float4* q4 = (const float4*)(query + (size_t)b * ND);
    const float4* w4 = (const float4*)(W_in + (size_t)e * ND);
    float acc = 0.f;
#pragma unroll 4
    for (int k = 0; k < ND / 4; k++) {
        float4 a = q4[k], w = w4[k];
        acc += a.x * w.x + a.y * w.y + a.z * w.z + a.w * w.w;
    }
    g_combined[(size_t)b * 2 * ND + ND + e] = acc;
}

// ---------------- B: scores[b,l] = dot(q[b], ctx[b,l,:]) ----------------
__global__ void kB(const float* __restrict__ ctx) {
    __shared__ float sq[ND];
    int b = blockIdx.y;
    int warp = threadIdx.x >> 5, lane = threadIdx.x & 31;
    ((float4*)sq)[threadIdx.x] = ((const float4*)(g_combined + (size_t)b * 2 * ND + ND))[threadIdx.x];
    __syncthreads();
    int l = blockIdx.x * 8 + warp;
    const float4* c4 = (const float4*)(ctx + ((size_t)(b * NL + l)) * ND);
    const float4* s4 = (const float4*)sq;
    float acc = 0.f;
#pragma unroll
    for (int k = 0; k < 8; k++) {
        int i = k * 32 + lane;
        float4 cv = c4[i], qv = s4[i];
        acc += cv.x * qv.x + cv.y * qv.y + cv.z * qv.z + cv.w * qv.w;
    }
#pragma unroll
    for (int o = 16; o > 0; o >>= 1) acc += __shfl_down_sync(0xffffffffu, acc, o);
    if (lane == 0) g_scores[b * NL + l] = acc;
}

// ---------------- C: softmax + expmap0/project (aw), bt ----------------
__global__ void kC(const float* __restrict__ dt, const float* __restrict__ cp,
                   const float* __restrict__ ab, float* __restrict__ out_aw) {
    __shared__ float sb[1024];
    int b = blockIdx.x, t = threadIdx.x;
    float c = cp[0], sc = sqrtf(c);
    float maxn = (1.0f - PROJ_EPS) / sc;

    float s = g_scores[b * NL + t];
    float mx = blk_max<1024>(s, sb);
    float e = expf(s - mx);
    float sum = blk_sum<1024>(e, sb);
    float aw = e / sum;

    float n = fmaxf(sqrtf(blk_sum<1024>(aw * aw, sb)), EPSF);
    float awh = tanhf(sc * n) / (sc * n) * aw;
    float nh = fmaxf(sqrtf(blk_sum<1024>(awh * awh, sb)), EPSF);
    if (nh > maxn) awh *= maxn / nh;
    g_aw[b * NL + t] = awh;
    out_aw[b * NL + t] = awh;

    float braw = expf(-ab[b] * dt[b * NL + t]);
    float bn = fmaxf(sqrtf(blk_sum<1024>(braw * braw, sb)), EPSF);
    float bth = tanhf(sc * bn) / (sc * bn) * braw;
    float bh = fmaxf(sqrtf(blk_sum<1024>(bth * bth, sb)), EPSF);
    if (bh > maxn) bth *= maxn / bh;
    g_bt[b * NL + t] = bth;
    if (t == 0) g_btn[b] = fminf(bh, maxn);
}

// ---------------- D1: partial column stats over an l-chunk ----------------
// grid (SPLIT, NB), 256 threads; thread owns 4 d via float4; block reads whole rows.
__global__ void kD1(const float* __restrict__ ctx) {
    __shared__ float saw[CH], sbt[CH];
    int b = blockIdx.y, s = blockIdx.x, t = threadIdx.x;
    int l0 = s * CH;
    if (t < CH) { saw[t] = g_aw[b * NL + l0 + t]; sbt[t] = g_bt[b * NL + l0 + t]; }
    __syncthreads();
    const float4* cb = (const float4*)(ctx + ((size_t)(b * NL + l0)) * ND) + t;

    float4 sx2 = {0,0,0,0}, swx2 = {0,0,0,0};
    float4 s2p = {0,0,0,0}, s2n = {0,0,0,0}, sxp = {0,0,0,0}, sxn = {0,0,0,0};

#pragma unroll 4
    for (int ll = 0; ll < CH; ll++) {
        float4 x = cb[(size_t)ll * (ND / 4)];
        float a = saw[ll], bt = sbt[ll];
        {
            float ax = a * x.x, g = bt * ax;
            sx2.x += x.x * x.x; swx2.x += ax * ax;
            if (g > 0.f) { s2p.x += g * g; sxp.x += ax * g; }
            else if (g < 0.f) { s2n.x += g * g; sxn.x += ax * g; }
        }
        {
            float ax = a * x.y, g = bt * ax;
            sx2.y += x.y * x.y; swx2.y += ax * ax;
            if (g > 0.f) { s2p.y += g * g; sxp.y += ax * g; }
            else if (g < 0.f) { s2n.y += g * g; sxn.y += ax * g; }
        }
        {
            float ax = a * x.z, g = bt * ax;
            sx2.z += x.z * x.z; swx2.z += ax * ax;
            if (g > 0.f) { s2p.z += g * g; sxp.z += ax * g; }
            else if (g < 0.f) { s2n.z += g * g; sxn.z += ax * g; }
        }
        {
            float ax = a * x.w, g = bt * ax;
            sx2.w += x.w * x.w; swx2.w += ax * ax;
            if (g > 0.f) { s2p.w += g * g; sxp.w += ax * g; }
            else if (g < 0.f) { s2n.w += g * g; sxn.w += ax * g; }
        }
    }
    size_t base = ((size_t)(b * SPLIT + s)) * ND;
    size_t stride = (size_t)NB * SPLIT * ND;
    ((float4*)(g_part + 0 * stride + base))[t] = sx2;
    ((float4*)(g_part + 1 * stride + base))[t] = swx2;
    ((float4*)(g_part + 2 * stride + base))[t] = s2p;
    ((float4*)(g_part + 3 * stride + base))[t] = s2n;
    ((float4*)(g_part + 4 * stride + base))[t] = sxp;
    ((float4*)(g_part + 5 * stride + base))[t] = sxn;
}

// ---------------- Df: finalize per-(b,d) scalars u, v, delta ----------------
__global__ void kDf(const float* __restrict__ cp, const float* __restrict__ ae) {
    int b = blockIdx.y;
    int d = blockIdx.x * 256 + threadIdx.x;
    size_t stride = (size_t)NB * SPLIT * ND;
    float sx2 = 0.f, swx2 = 0.f, s2p = 0.f, s2n = 0.f, sxp = 0.f, sxn = 0.f;
#pragma unroll
    for (int s = 0; s < SPLIT; s++) {
        size_t base = ((size_t)(b * SPLIT + s)) * ND + d;
        sx2  += g_part[0 * stride + base];
        swx2 += g_part[1 * stride + base];
        s2p  += g_part[2 * stride + base];
        s2n  += g_part[3 * stride + base];
        sxp  += g_part[4 * stride + base];
        sxn  += g_part[5 * stride + base];
    }

    float c = cp[0], sc = sqrtf(c);
    float maxn = (1.0f - PROJ_EPS) / sc;

    // step 5: mix = project(mobius_pointwise_mul(aw, ctx_t)) -> alpha*aw*ctx
    float xn   = fmaxf(sqrtf(sx2), EPSF);
    float wxnr = sqrtf(swx2);
    float wxn  = fmaxf(wxnr, EPSF);
    float s1 = tanhf(wxn / xn * artanh_c(sc * xn)) / (wxn * sc);
    float n1 = fmaxf(fabsf(s1) * wxnr, EPSF);
    float alpha = s1 * (n1 > maxn ? maxn / n1 : 1.0f);
    float nmixr = fabsf(alpha) * wxnr;

    // step 7: tmp = project(mobius_pointwise_mul(ae, mix)) -> T*aw*ctx
    float aeb = ae[b];
    float xn7 = fmaxf(nmixr, EPSF);
    float wxn7 = fmaxf(fabsf(aeb) * nmixr, EPSF);
    float t7 = tanhf(wxn7 / xn7 * artanh_c(sc * xn7)) / (wxn7 * sc);
    float n7 = fmaxf(fabsf(t7 * aeb) * nmixr, EPSF);
    float T = t7 * aeb * alpha * (n7 > maxn ? maxn / n7 : 1.0f);

    // step 8: tmp = project(mobius_pointwise_mul(tmp, bt)) -> dl*aw*bt*ctx
    float m8r = sqrtf(s2p + s2n);
    float xn8 = g_btn[b];
    float wxn8 = fmaxf(fabsf(T) * m8r, EPSF);
    float t8 = tanhf(wxn8 / xn8 * artanh_c(sc * xn8)) / (wxn8 * sc);
    float dpre = t8 * T;
    float n8 = fmaxf(fabsf(dpre) * m8r, EPSF);
    float dl = dpre * (n8 > maxn ? maxn / n8 : 1.0f);

    // step 10: mix = project(mobius_add(mix, relu(tmp)))
    float x2 = alpha * alpha * swx2;
    bool pos = (dl > 0.f);
    float S2 = pos ? s2p : s2n;
    float SX = pos ? sxp : sxn;
    float y2 = dl * dl * S2;
    float xy = alpha * dl * SX;
    float A  = 1.0f + 2.0f * c * xy + c * y2;
    float Bc = 1.0f - c * x2;
    float den = fmaxf(1.0f + 2.0f * c * xy + c * c * x2 * y2, EPSF);
    float nn2 = (A * A * x2 + 2.0f * A * Bc * xy + Bc * Bc * y2) / (den * den);
    float n10 = fmaxf(sqrtf(fmaxf(nn2, 0.f)), EPSF);
    float p10 = (n10 > maxn) ? maxn / n10 : 1.0f;

    g_u[b * ND + d]  = p10 * A * alpha / den;
    g_v[b * ND + d]  = p10 * Bc * dl / den;
    g_dl[b * ND + d] = dl;
}

// ---------------- E1: lambda[b,l] (warp per l, shuffle reduce) ----------------
__global__ void kE1(const float* __restrict__ ctx, const float* __restrict__ cp) {
    int b = blockIdx.y;
    int warp = threadIdx.x >> 5, lane = threadIdx.x & 31;
    int l = blockIdx.x * 8 + warp;
    float c = cp[0];
    float awl = g_aw[b * NL + l], btl = g_bt[b * NL + l];
    const float4* x4 = (const float4*)(ctx + ((size_t)(b * NL + l)) * ND);
    const float4* u4 = (const float4*)(g_u + (size_t)b * ND);
    const float4* v4 = (const float4*)(g_v + (size_t)b * ND);
    const float4* d4 = (const float4*)(g_dl + (size_t)b * ND);
    float s = 0.f;
#pragma unroll
    for (int k = 0; k < 8; k++) {
        int i = k * 32 + lane;
        float4 x = x4[i], u = u4[i], v = v4[i], dl = d4[i];
        float g, m;
        g = awl * btl * x.x; m = u.x * awl * x.x + ((dl.x * g) > 0.f ? v.x * g : 0.f); s += m * m;
        g = awl * btl * x.y; m = u.y * awl * x.y + ((dl.y * g) > 0.f ? v.y * g : 0.f); s += m * m;
        g = awl * btl * x.z; m = u.z * awl * x.z + ((dl.z * g) > 0.f ? v.z * g : 0.f); s += m * m;
        g = awl * btl * x.w; m = u.w * awl * x.w + ((dl.w * g) > 0.f ? v.w * g : 0.f); s += m * m;
    }
#pragma unroll
    for (int o = 16; o > 0; o >>= 1) s += __shfl_down_sync(0xffffffffu, s, o);
    if (lane == 0) g_lam[b * NL + l] = 2.0f / fmaxf(1.0f - c * s, EPSF);
}

// ---------------- E2: partial nom over an l-chunk ----------------
__global__ void kE21(const float* __restrict__ ctx) {
    __shared__ float saw[CH], sbt[CH], slam[CH];
    int b = blockIdx.y, s = blockIdx.x, t = threadIdx.x;
    int l0 = s * CH;
    if (t < CH) {
        saw[t] = g_aw[b * NL + l0 + t];
        sbt[t] = g_bt[b * NL + l0 + t];
        slam[t] = g_lam[b * NL + l0 + t];
    }
    __syncthreads();
    int d = 4 * t;
    const float4* cb = (const float4*)(ctx + ((size_t)(b * NL + l0)) * ND) + t;
    float4 u = ((const float4*)(g_u + (size_t)b * ND))[t];
    float4 v = ((const float4*)(g_v + (size_t)b * ND))[t];
    float4 dl = ((const float4*)(g_dl + (size_t)b * ND))[t];
    (void)d;

    float4 nom = {0,0,0,0};
#pragma unroll 4
    for (int ll = 0; ll < CH; ll++) {
        float4 x = cb[(size_t)ll * (ND / 4)];
        float a = saw[ll], bt = sbt[ll], lam = slam[ll];
        float g, m;
        g = a * bt * x.x; m = u.x * a * x.x + ((dl.x * g) > 0.f ? v.x * g : 0.f); nom.x += lam * m;
        g = a * bt * x.y; m = u.y * a * x.y + ((dl.y * g) > 0.f ? v.y * g : 0.f); nom.y += lam * m;
        g = a * bt * x.z; m = u.z * a * x.z + ((dl.z * g) > 0.f ? v.z * g : 0.f); nom.z += lam * m;
        g = a * bt * x.w; m = u.w * a * x.w + ((dl.w * g) > 0.f ? v.w * g : 0.f); nom.w += lam * m;
    }
    ((float4*)(g_nomp + ((size_t)(b * SPLIT + s)) * ND))[t] = nom;
}

// ---------------- F: midpoint epilogue (sums nom partials) ----------------
__global__ void kF(const float* __restrict__ cp) {
    __shared__ float sb[1024];
    int b = blockIdx.x, t = threadIdx.x;
    float c = cp[0], sc = sqrtf(c);
    float lam = g_lam[b * NL + t];
    float den = blk_sum<1024>(lam - 1.0f, sb);
    den = (den >= 0.f) ? fmaxf(den, 1e-10f) : fminf(den, -1e-10f);

    float nom = 0.f;
#pragma unroll
    for (int s = 0; s < SPLIT; s++)
        nom += g_nomp[((size_t)(b * SPLIT + s)) * ND + t];

    float tm = nom / den;
    float nr = sqrtf(blk_sum<1024>(tm * tm, sb));
    float n = fmaxf(nr, EPSF);
    float cf = tanhf(0.5f * artanh_c(sc * n)) / (sc * n);
    float nf = fmaxf(fabsf(cf) * nr, EPSF);
    float lc = artanh_c(sc * nf) / (sc * nf);
    g_combined[(size_t)b * 2 * ND + t] = lc * cf * tm;
}

// ---------------- G: out = tanh(combined @ W_out^T) ----------------
__global__ void kG(const float* __restrict__ W_out, float* __restrict__ out) {
    int b = threadIdx.x;
    int d = blockIdx.x * 4 + threadIdx.y;
    const float4* cb4 = (const float4*)(g_combined + (size_t)b * 2 * ND);
    const float4* w4  = (const float4*)(W_out + (size_t)d * 2 * ND);
    float acc = 0.f;
#pragma unroll 4
    for (int k = 0; k < 2 * ND / 4; k++) {
        float4 a = cb4[k], w = w4[k];
        acc += a.x * w.x + a.y * w.y + a.z * w.z + a.w * w.w;
    }
    out[b * ND + d] = tanhf(acc);
}

// ---------------- launch ----------------
extern "C" void kernel_launch(void* const* d_in, const int* in_sizes, int n_in,
                              void* d_out, int out_size) {
    const float* query = (const float*)d_in[0];
    const float* ctx   = (const float*)d_in[1];
    const float* dt    = (const float*)d_in[2];
    const float* cp    = (const float*)d_in[3];
    const float* W_in  = (const float*)d_in[4];
    const float* W_out = (const float*)d_in[5];
    const float* ae    = (const float*)d_in[6];
    const float* ab    = (const float*)d_in[7];
    float* out = (float*)d_out;

    kA<<<ND / 4, dim3(64, 4)>>>(query, W_in);
    kB<<<dim3(NL / 8, NB), 256>>>(ctx);
    kC<<<NB, 1024>>>(dt, cp, ab, out + NB * ND);
    kD1<<<dim3(SPLIT, NB), 256>>>(ctx);
    kDf<<<dim3(ND / 256, NB), 256>>>(cp, ae);
    kE1<<<dim3(NL / 8, NB), 256>>>(ctx, cp);
    kE21<<<dim3(SPLIT, NB), 256>>>(ctx);
    kF<<<NB, 1024>>>(cp);
    kG<<<ND / 4, dim3(64, 4)>>>(W_out, out);
}